// round 13
// baseline (speedup 1.0000x reference)
#include <cuda_runtime.h>

#define S    512
#define C    192
#define B    2
#define BW   21
#define HALF 10
#define KS   7

#define NPLANES   (B * C)          // 384
#define NFIX      96               // fixup blocks (b x 48 d-tiles of 4)
#define COPY_BLKS 12288            // 25,165,824 float4 / 2048
#define FAT_BLKS  (NPLANES + NFIX + COPY_BLKS)

// Scratch (allocation-free rule: __device__ globals)
__device__ float    g_conv [NPLANES * S];      // band after depthwise conv
__device__ float    g_diagf[NPLANES * S * 4];  // float4 around (r,r), as floats
__device__ unsigned g_k1done  = 0;             // K1 completion counter
__device__ unsigned g_fixdone = 0;             // fixup completion counter (reset)

// ---------------------------------------------------------------------------
// Fat kernel (512 threads), three roles by blockIdx.x:
//   [0, 384):      K1 — band mean + depthwise conv + diagonal-float4 stash.
//                  Loads are PREDICATED to the 21-wide band (contiguous lane
//                  ranges -> 1-3 sectors/row instead of 4; ~17MB DRAM saved).
//   [384, 480):    FIX — spins until all K1 done, then pointwise GEMV
//                  (L2-warm) + softmax + diagonal out-writes, overlapped
//                  with the copy.
//   [480, ...):    COPY — streaming x -> out (4 x float4/thread), skipping
//                  diagonal vectors.
// ---------------------------------------------------------------------------
__global__ void __launch_bounds__(512) fat_kernel(
        const float*  __restrict__ x,
        const float*  __restrict__ conv_w,
        const float*  __restrict__ point_w,
        const float*  __restrict__ point_b,
        const float4* __restrict__ x4,
        float4*       __restrict__ out4) {
    const int tid = threadIdx.x;

    if (blockIdx.x < NPLANES) {
        // ======================= K1 =========================================
        __shared__ float band_s[S];

        const int bc   = blockIdx.x;               // b*C + c
        const int c    = bc % C;
        const int w    = tid >> 5;                 // warp 0..15
        const int lane = tid & 31;
        const int c0   = w << 5;
        const int j    = c0 + lane;
        const float* plane = x + ((size_t)bc << 18);

        float sum = 0.f;
        #pragma unroll
        for (int t = -10; t <= 41; t++) {
            const int r = c0 + t;
            const int d = t - lane;                // r - j
            // Predicated: only in-band lanes (contiguous range per t) load.
            // Stash lanes have |d|<=3, a subset of the band -> still covered.
            if (r >= 0 && r < S && d >= -10 && d <= 10) {
                const float v = plane[r * S + j];
                if (t >= 0 && t <= 31 && (t >> 2) == (lane >> 2))
                    g_diagf[(((bc << 9) + r) << 2) + (lane & 3)] = v;
                sum += v;
            }
        }
        band_s[j] = sum * (1.0f / (float)BW);
        __syncthreads();

        float wgt[KS];
        #pragma unroll
        for (int k = 0; k < KS; k++) wgt[k] = conv_w[c * KS + k];
        float acc = 0.f;
        #pragma unroll
        for (int k = 0; k < KS; k++) {
            const int jj = j + k - 3;
            if (jj >= 0 && jj < S) acc += band_s[jj] * wgt[k];
        }
        g_conv[(bc << 9) + j] = acc;

        // signal completion (release)
        __threadfence();
        __syncthreads();
        if (tid == 0) atomicAdd(&g_k1done, 1u);

    } else if (blockIdx.x < NPLANES + NFIX) {
        // ======================= FIX ========================================
        __shared__ float wtile[4 * C];       // 3 KB
        __shared__ float part[16 * 4];
        __shared__ float bcast[4];
        __shared__ float attn_s[4 * S];      // 8 KB

        const int blk  = blockIdx.x - NPLANES;
        const int b    = blk / 48;
        const int g    = blk - b * 48;       // d-tile, d in [4g, 4g+4)
        const int s    = tid;
        const int w    = s >> 5;
        const int lane = s & 31;

        // Preload weights while waiting (no g_conv dependency).
        for (int i = s; i < 4 * C; i += 512) {
            const int d = i / C, cc = i - d * C;
            wtile[i] = point_w[(g * 4 + d) * C + cc];
        }

        // wait for all K1 blocks (acquire)
        if (tid == 0) {
            volatile unsigned* p = &g_k1done;
            while (*p < (unsigned)NPLANES) __nanosleep(64);
        }
        __syncthreads();
        __threadfence();

        const float* cb = g_conv + b * C * S + s;
        float acc[4];
        #pragma unroll
        for (int d = 0; d < 4; d++) acc[d] = point_b[g * 4 + d];

        // GEMV over C=192, 12 batches of 16 staged loads (MLP=16, L2-warm).
        #pragma unroll 1
        for (int cc = 0; cc < C; cc += 16) {
            float vbuf[16];
            #pragma unroll
            for (int u = 0; u < 16; u++)
                vbuf[u] = cb[(cc + u) * S];
            #pragma unroll
            for (int u = 0; u < 16; u++) {
                #pragma unroll
                for (int d = 0; d < 4; d++)
                    acc[d] += vbuf[u] * wtile[d * C + cc + u];
            }
        }

        // ---- max over s ----
        #pragma unroll
        for (int d = 0; d < 4; d++) {
            float v = acc[d];
            #pragma unroll
            for (int off = 16; off > 0; off >>= 1)
                v = fmaxf(v, __shfl_xor_sync(0xffffffffu, v, off));
            if (lane == 0) part[w * 4 + d] = v;
        }
        __syncthreads();
        if (s < 4) {
            float v = part[s];
            #pragma unroll
            for (int ww = 1; ww < 16; ww++) v = fmaxf(v, part[ww * 4 + s]);
            bcast[s] = v;
        }
        __syncthreads();
        float m[4];
        #pragma unroll
        for (int d = 0; d < 4; d++) m[d] = bcast[d];
        __syncthreads();

        // ---- exp + sum over s ----
        float e[4];
        #pragma unroll
        for (int d = 0; d < 4; d++) {
            e[d] = __expf(acc[d] - m[d]);
            float v = e[d];
            #pragma unroll
            for (int off = 16; off > 0; off >>= 1)
                v += __shfl_xor_sync(0xffffffffu, v, off);
            if (lane == 0) part[w * 4 + d] = v;
        }
        __syncthreads();
        if (s < 4) {
            float v = part[s];
            #pragma unroll
            for (int ww = 1; ww < 16; ww++) v += part[ww * 4 + s];
            bcast[s] = 1.0f / v;
        }
        __syncthreads();

        #pragma unroll
        for (int d = 0; d < 4; d++) attn_s[d * S + s] = e[d] * bcast[d];
        __syncthreads();

        // ---- diagonal-vector write: dense stash load, scattered store ------
        #pragma unroll
        for (int d = 0; d < 4; d++) {
            const int plane = b * C + g * 4 + d;
            const int r     = s;                          // row 0..511
            float4 val = *reinterpret_cast<const float4*>(
                              g_diagf + ((((plane << 9) + r)) << 2));
            const float a = attn_s[d * S + r];
            const int dr  = r & 3;
            if      (dr == 0) val.x *= a;
            else if (dr == 1) val.y *= a;
            else if (dr == 2) val.z *= a;
            else              val.w *= a;
            // element index of (r, r): v4 = (plane<<16) + (r<<7) + (r>>2)
            out4[(plane << 16) + (r << 7) + (r >> 2)] = val;
        }

        // ---- counter reset for graph replay determinism --------------------
        __syncthreads();
        if (tid == 0) {
            const unsigned prev = atomicAdd(&g_fixdone, 1u);
            if (prev == NFIX - 1) {       // last fixup block: reset both
                g_fixdone = 0;
                g_k1done  = 0;
                __threadfence();
            }
        }

    } else {
        // ======================= COPY =======================================
        const int base = (blockIdx.x - NPLANES - NFIX) * 2048 + tid;
        float4 v0 = __ldcs(x4 + base);
        float4 v1 = __ldcs(x4 + base +  512);
        float4 v2 = __ldcs(x4 + base + 1024);
        float4 v3 = __ldcs(x4 + base + 1536);

        #pragma unroll
        for (int i = 0; i < 4; i++) {
            const int v  = base + i * 512;
            const int e  = v << 2;               // element index (< 2^27)
            const int j0 = e & (S - 1);          // column of lane 0
            const int r  = (e >> 9) & (S - 1);
            const int dr = r - j0;
            if ((unsigned)dr >= 4u) {            // skip diagonal-carrying vecs
                const float4 val = (i == 0) ? v0 : (i == 1) ? v1 :
                                   (i == 2) ? v2 : v3;
                __stcs(out4 + v, val);
            }
        }
    }
}

// ---------------------------------------------------------------------------
extern "C" void kernel_launch(void* const* d_in, const int* in_sizes, int n_in,
                              void* d_out, int out_size) {
    const float* x       = (const float*)d_in[0];   // [2,192,512,512]
    const float* conv_w  = (const float*)d_in[1];   // [192,1,7]
    const float* point_w = (const float*)d_in[2];   // [192,192]
    const float* point_b = (const float*)d_in[3];   // [192]

    fat_kernel<<<FAT_BLKS, 512>>>(x, conv_w, point_w, point_b,
                                  (const float4*)x, (float4*)d_out);
}

// round 14
// speedup vs baseline: 1.1148x; 1.1148x over previous
#include <cuda_runtime.h>

#define S    512
#define C    192
#define B    2
#define BW   21
#define HALF 10
#define KS   7

#define NPLANES   (B * C)          // 384
#define NFIX      96               // fixup blocks (b x 48 d-tiles of 4)
#define COPY_BLKS 12288            // 25,165,824 float4 / 2048
#define FAT_BLKS  (NPLANES + NFIX + COPY_BLKS)

// Scratch (allocation-free rule: __device__ globals)
__device__ float    g_conv [NPLANES * S];      // band after depthwise conv
__device__ float    g_diagf[NPLANES * S * 4];  // float4 around (r,r), as floats
__device__ unsigned g_k1done  = 0;             // K1 completion counter
__device__ unsigned g_fixdone = 0;             // fixup completion counter (reset)

// ---------------------------------------------------------------------------
// Fat kernel (512 threads), three roles by blockIdx.x:
//   [0, 384):   K1 — band mean + depthwise conv + diagonal-float4 stash.
//               NEW: K1 also STORES its loaded full lines to out (rows
//               r = c0-10..c0+41 per column-block c0), except the exact
//               diagonal element. Deduplicates the copy's read of the band
//               region (~41 MB DRAM saved, full-line pattern preserved).
//   [384,480):  FIX — spins until all K1 done, then pointwise GEMV (L2-warm)
//               + softmax + diagonal float4 out-writes.
//   [480,...):  COPY — streaming x -> out, SKIPPING (load+store) all vectors
//               in the K1-covered band region.
// ---------------------------------------------------------------------------
__global__ void __launch_bounds__(512) fat_kernel(
        const float*  __restrict__ x,
        const float*  __restrict__ conv_w,
        const float*  __restrict__ point_w,
        const float*  __restrict__ point_b,
        const float4* __restrict__ x4,
        float4*       __restrict__ out4,
        float*        __restrict__ out) {
    const int tid = threadIdx.x;

    if (blockIdx.x < NPLANES) {
        // ======================= K1 =========================================
        __shared__ float band_s[S];

        const int bc   = blockIdx.x;               // b*C + c
        const int c    = bc % C;
        const int w    = tid >> 5;                 // warp 0..15
        const int lane = tid & 31;
        const int c0   = w << 5;
        const int j    = c0 + lane;
        const float* plane = x + ((size_t)bc << 18);
        float* oplane      = out + ((size_t)bc << 18);

        float sum = 0.f;
        #pragma unroll
        for (int t = -10; t <= 41; t++) {
            const int r = c0 + t;
            if (r >= 0 && r < S) {
                const float v = plane[r * S + j];  // full-line coalesced load
                // stash diagonal float4 pieces: lanes with lane>>2 == t>>2
                if (t >= 0 && t <= 31 && (t >> 2) == (lane >> 2))
                    g_diagf[(((bc << 9) + r) << 2) + (lane & 3)] = v;
                const int d = t - lane;            // r - j
                if (d >= -10 && d <= 10) sum += v;
                // store this line to out (copy role skips it); the exact
                // diagonal element (t==lane) is owned by FIX.
                if (!(t >= 0 && t <= 31 && t == lane))
                    out[((size_t)bc << 18) + r * S + j] = v;
            }
        }
        (void)oplane;
        band_s[j] = sum * (1.0f / (float)BW);
        __syncthreads();

        float wgt[KS];
        #pragma unroll
        for (int k = 0; k < KS; k++) wgt[k] = conv_w[c * KS + k];
        float acc = 0.f;
        #pragma unroll
        for (int k = 0; k < KS; k++) {
            const int jj = j + k - 3;
            if (jj >= 0 && jj < S) acc += band_s[jj] * wgt[k];
        }
        g_conv[(bc << 9) + j] = acc;

        // signal completion (release)
        __threadfence();
        __syncthreads();
        if (tid == 0) atomicAdd(&g_k1done, 1u);

    } else if (blockIdx.x < NPLANES + NFIX) {
        // ======================= FIX ========================================
        __shared__ float wtile[4 * C];       // 3 KB
        __shared__ float part[16 * 4];
        __shared__ float bcast[4];
        __shared__ float attn_s[4 * S];      // 8 KB

        const int blk  = blockIdx.x - NPLANES;
        const int b    = blk / 48;
        const int g    = blk - b * 48;       // d-tile, d in [4g, 4g+4)
        const int s    = tid;
        const int w    = s >> 5;
        const int lane = s & 31;

        // Preload weights while waiting (no g_conv dependency).
        for (int i = s; i < 4 * C; i += 512) {
            const int d = i / C, cc = i - d * C;
            wtile[i] = point_w[(g * 4 + d) * C + cc];
        }

        // wait for all K1 blocks (acquire)
        if (tid == 0) {
            volatile unsigned* p = &g_k1done;
            while (*p < (unsigned)NPLANES) __nanosleep(64);
        }
        __syncthreads();
        __threadfence();

        const float* cb = g_conv + b * C * S + s;
        float acc[4];
        #pragma unroll
        for (int d = 0; d < 4; d++) acc[d] = point_b[g * 4 + d];

        // GEMV over C=192, 12 batches of 16 staged loads (MLP=16, L2-warm).
        #pragma unroll 1
        for (int cc = 0; cc < C; cc += 16) {
            float vbuf[16];
            #pragma unroll
            for (int u = 0; u < 16; u++)
                vbuf[u] = cb[(cc + u) * S];
            #pragma unroll
            for (int u = 0; u < 16; u++) {
                #pragma unroll
                for (int d = 0; d < 4; d++)
                    acc[d] += vbuf[u] * wtile[d * C + cc + u];
            }
        }

        // ---- max over s ----
        #pragma unroll
        for (int d = 0; d < 4; d++) {
            float v = acc[d];
            #pragma unroll
            for (int off = 16; off > 0; off >>= 1)
                v = fmaxf(v, __shfl_xor_sync(0xffffffffu, v, off));
            if (lane == 0) part[w * 4 + d] = v;
        }
        __syncthreads();
        if (s < 4) {
            float v = part[s];
            #pragma unroll
            for (int ww = 1; ww < 16; ww++) v = fmaxf(v, part[ww * 4 + s]);
            bcast[s] = v;
        }
        __syncthreads();
        float m[4];
        #pragma unroll
        for (int d = 0; d < 4; d++) m[d] = bcast[d];
        __syncthreads();

        // ---- exp + sum over s ----
        float e[4];
        #pragma unroll
        for (int d = 0; d < 4; d++) {
            e[d] = __expf(acc[d] - m[d]);
            float v = e[d];
            #pragma unroll
            for (int off = 16; off > 0; off >>= 1)
                v += __shfl_xor_sync(0xffffffffu, v, off);
            if (lane == 0) part[w * 4 + d] = v;
        }
        __syncthreads();
        if (s < 4) {
            float v = part[s];
            #pragma unroll
            for (int ww = 1; ww < 16; ww++) v += part[ww * 4 + s];
            bcast[s] = 1.0f / v;
        }
        __syncthreads();

        #pragma unroll
        for (int d = 0; d < 4; d++) attn_s[d * S + s] = e[d] * bcast[d];
        __syncthreads();

        // ---- diagonal-vector write: dense stash load, scattered store ------
        #pragma unroll
        for (int d = 0; d < 4; d++) {
            const int plane = b * C + g * 4 + d;
            const int r     = s;                          // row 0..511
            float4 val = *reinterpret_cast<const float4*>(
                              g_diagf + ((((plane << 9) + r)) << 2));
            const float a = attn_s[d * S + r];
            const int dr  = r & 3;
            if      (dr == 0) val.x *= a;
            else if (dr == 1) val.y *= a;
            else if (dr == 2) val.z *= a;
            else              val.w *= a;
            // element index of (r, r): v4 = (plane<<16) + (r<<7) + (r>>2)
            out4[(plane << 16) + (r << 7) + (r >> 2)] = val;
        }

        // ---- counter reset for graph replay determinism --------------------
        __syncthreads();
        if (tid == 0) {
            const unsigned prev = atomicAdd(&g_fixdone, 1u);
            if (prev == NFIX - 1) {       // last fixup block: reset both
                g_fixdone = 0;
                g_k1done  = 0;
                __threadfence();
            }
        }

    } else {
        // ======================= COPY =======================================
        // Skip (load AND store) any vector whose row lies in the K1 band of
        // its column block: r - (j0 & ~31) in [-10, 41]. These are contiguous
        // vector runs, so whole lines are skipped (no partial-sector loads).
        const int base = (blockIdx.x - NPLANES - NFIX) * 2048 + tid;

        bool   keep[4];
        float4 val[4];
        #pragma unroll
        for (int i = 0; i < 4; i++) {
            const int v   = base + i * 512;
            const int e   = v << 2;              // element index (< 2^27)
            const int j0  = e & (S - 1);         // column of lane 0
            const int r   = (e >> 9) & (S - 1);
            const int dr2 = r - (j0 & ~31);
            keep[i] = ((unsigned)(dr2 + 10) > 51u);
            if (keep[i]) val[i] = __ldcs(x4 + v);
        }
        #pragma unroll
        for (int i = 0; i < 4; i++) {
            if (keep[i]) __stcs(out4 + base + i * 512, val[i]);
        }
    }
}

// ---------------------------------------------------------------------------
extern "C" void kernel_launch(void* const* d_in, const int* in_sizes, int n_in,
                              void* d_out, int out_size) {
    const float* x       = (const float*)d_in[0];   // [2,192,512,512]
    const float* conv_w  = (const float*)d_in[1];   // [192,1,7]
    const float* point_w = (const float*)d_in[2];   // [192,192]
    const float* point_b = (const float*)d_in[3];   // [192]

    fat_kernel<<<FAT_BLKS, 512>>>(x, conv_w, point_w, point_b,
                                  (const float4*)x, (float4*)d_out,
                                  (float*)d_out);
}

// round 15
// speedup vs baseline: 1.1212x; 1.0058x over previous
#include <cuda_runtime.h>

#define S    512
#define C    192
#define B    2
#define BW   21
#define HALF 10
#define KS   7

#define NPLANES   (B * C)          // 384
#define NFIX      96               // fixup groups (b x 48 d-tiles of 4)
#define COPY_BLKS 12288            // 25,165,824 float4 / 2048
#define FAT_BLKS  (NPLANES + COPY_BLKS)

// Scratch (allocation-free rule: __device__ globals)
__device__ float    g_conv [NPLANES * S];      // band after depthwise conv
__device__ float    g_diagf[NPLANES * S * 4];  // float4 around (r,r), as floats
__device__ unsigned g_k1done  = 0;             // K1 completion counter
__device__ unsigned g_fixdone = 0;             // fixup completion counter (reset)

// ---------------------------------------------------------------------------
// Fat kernel (512 threads), roles by blockIdx.x:
//   [0, 384):   K1 — band mean + depthwise conv + diagonal-float4 stash +
//               stores its loaded band lines to out (copy skips them).
//               THEN blocks [0, 96) continue as FIX: spin until all K1 done,
//               pointwise GEMV (L2-warm) + softmax + diagonal float4 writes.
//   [384, ...): COPY — streaming x -> out, skipping the K1-covered band
//               region entirely (load AND store).
// ---------------------------------------------------------------------------
__global__ void __launch_bounds__(512) fat_kernel(
        const float*  __restrict__ x,
        const float*  __restrict__ conv_w,
        const float*  __restrict__ point_w,
        const float*  __restrict__ point_b,
        const float4* __restrict__ x4,
        float4*       __restrict__ out4,
        float*        __restrict__ out) {
    const int tid = threadIdx.x;

    if (blockIdx.x < NPLANES) {
        // ======================= K1 =========================================
        __shared__ float band_s[S];

        const int bc   = blockIdx.x;               // b*C + c
        const int c    = bc % C;
        const int w    = tid >> 5;                 // warp 0..15
        const int lane = tid & 31;
        const int c0   = w << 5;
        const int j    = c0 + lane;
        const float* plane = x + ((size_t)bc << 18);

        float sum = 0.f;
        #pragma unroll
        for (int t = -10; t <= 41; t++) {
            const int r = c0 + t;
            if (r >= 0 && r < S) {
                const float v = plane[r * S + j];  // full-line coalesced load
                // stash diagonal float4 pieces: lanes with lane>>2 == t>>2
                if (t >= 0 && t <= 31 && (t >> 2) == (lane >> 2))
                    g_diagf[(((bc << 9) + r) << 2) + (lane & 3)] = v;
                const int d = t - lane;            // r - j
                if (d >= -10 && d <= 10) sum += v;
                // store this line to out (copy role skips it); the exact
                // diagonal element (t==lane) is owned by FIX.
                if (!(t >= 0 && t <= 31 && t == lane))
                    out[((size_t)bc << 18) + r * S + j] = v;
            }
        }
        band_s[j] = sum * (1.0f / (float)BW);
        __syncthreads();

        {
            float wgt[KS];
            #pragma unroll
            for (int k = 0; k < KS; k++) wgt[k] = conv_w[c * KS + k];
            float acc = 0.f;
            #pragma unroll
            for (int k = 0; k < KS; k++) {
                const int jj = j + k - 3;
                if (jj >= 0 && jj < S) acc += band_s[jj] * wgt[k];
            }
            g_conv[(bc << 9) + j] = acc;
        }

        // signal completion (release)
        __threadfence();
        __syncthreads();
        if (tid == 0) atomicAdd(&g_k1done, 1u);

        if (blockIdx.x >= NFIX) return;

        // ======================= FIX (blocks 0..95 continue) ================
        __shared__ float wtile[4 * C];       // 3 KB
        __shared__ float part[16 * 4];
        __shared__ float bcast[4];
        __shared__ float attn_s[4 * S];      // 8 KB

        const int blk = blockIdx.x;
        const int b   = blk / 48;
        const int g   = blk - b * 48;        // d-tile, d in [4g, 4g+4)
        const int s   = tid;

        // Preload weights (no g_conv dependency) before spinning.
        for (int i = s; i < 4 * C; i += 512) {
            const int d = i / C, cc = i - d * C;
            wtile[i] = point_w[(g * 4 + d) * C + cc];
        }

        // wait for all K1 blocks (acquire)
        if (tid == 0) {
            volatile unsigned* p = &g_k1done;
            while (*p < (unsigned)NPLANES) __nanosleep(64);
        }
        __syncthreads();
        __threadfence();

        const float* cb = g_conv + b * C * S + s;
        float acc[4];
        #pragma unroll
        for (int d = 0; d < 4; d++) acc[d] = point_b[g * 4 + d];

        // GEMV over C=192, 12 batches of 16 staged loads (MLP=16, L2-warm).
        #pragma unroll 1
        for (int cc = 0; cc < C; cc += 16) {
            float vbuf[16];
            #pragma unroll
            for (int u = 0; u < 16; u++)
                vbuf[u] = cb[(cc + u) * S];
            #pragma unroll
            for (int u = 0; u < 16; u++) {
                #pragma unroll
                for (int d = 0; d < 4; d++)
                    acc[d] += vbuf[u] * wtile[d * C + cc + u];
            }
        }

        // ---- max over s ----
        #pragma unroll
        for (int d = 0; d < 4; d++) {
            float v = acc[d];
            #pragma unroll
            for (int off = 16; off > 0; off >>= 1)
                v = fmaxf(v, __shfl_xor_sync(0xffffffffu, v, off));
            if (lane == 0) part[w * 4 + d] = v;
        }
        __syncthreads();
        if (s < 4) {
            float v = part[s];
            #pragma unroll
            for (int ww = 1; ww < 16; ww++) v = fmaxf(v, part[ww * 4 + s]);
            bcast[s] = v;
        }
        __syncthreads();
        float m[4];
        #pragma unroll
        for (int d = 0; d < 4; d++) m[d] = bcast[d];
        __syncthreads();

        // ---- exp + sum over s ----
        float e[4];
        #pragma unroll
        for (int d = 0; d < 4; d++) {
            e[d] = __expf(acc[d] - m[d]);
            float v = e[d];
            #pragma unroll
            for (int off = 16; off > 0; off >>= 1)
                v += __shfl_xor_sync(0xffffffffu, v, off);
            if (lane == 0) part[w * 4 + d] = v;
        }
        __syncthreads();
        if (s < 4) {
            float v = part[s];
            #pragma unroll
            for (int ww = 1; ww < 16; ww++) v += part[ww * 4 + s];
            bcast[s] = 1.0f / v;
        }
        __syncthreads();

        #pragma unroll
        for (int d = 0; d < 4; d++) attn_s[d * S + s] = e[d] * bcast[d];
        __syncthreads();

        // ---- diagonal-vector write: dense stash load, scattered store ------
        #pragma unroll
        for (int d = 0; d < 4; d++) {
            const int plane_o = b * C + g * 4 + d;
            const int r       = s;                        // row 0..511
            float4 val = *reinterpret_cast<const float4*>(
                              g_diagf + ((((plane_o << 9) + r)) << 2));
            const float a = attn_s[d * S + r];
            const int dr  = r & 3;
            if      (dr == 0) val.x *= a;
            else if (dr == 1) val.y *= a;
            else if (dr == 2) val.z *= a;
            else              val.w *= a;
            // element index of (r, r): v4 = (plane<<16) + (r<<7) + (r>>2)
            out4[(plane_o << 16) + (r << 7) + (r >> 2)] = val;
        }

        // ---- counter reset for graph replay determinism --------------------
        __syncthreads();
        if (tid == 0) {
            const unsigned prev = atomicAdd(&g_fixdone, 1u);
            if (prev == NFIX - 1) {       // last fixup block: reset both
                g_fixdone = 0;
                g_k1done  = 0;
                __threadfence();
            }
        }

    } else {
        // ======================= COPY =======================================
        // Skip (load AND store) any vector whose row lies in the K1 band of
        // its column block: r - (j0 & ~31) in [-10, 41]. Contiguous vector
        // runs -> whole lines skipped (no partial-sector poison).
        const int base = (blockIdx.x - NPLANES) * 2048 + tid;

        bool   keep[4];
        float4 val[4];
        #pragma unroll
        for (int i = 0; i < 4; i++) {
            const int v   = base + i * 512;
            const int e   = v << 2;              // element index (< 2^27)
            const int j0  = e & (S - 1);         // column of lane 0
            const int r   = (e >> 9) & (S - 1);
            const int dr2 = r - (j0 & ~31);
            keep[i] = ((unsigned)(dr2 + 10) > 51u);
            if (keep[i]) val[i] = __ldcs(x4 + v);
        }
        #pragma unroll
        for (int i = 0; i < 4; i++) {
            if (keep[i]) __stcs(out4 + base + i * 512, val[i]);
        }
    }
}

// ---------------------------------------------------------------------------
extern "C" void kernel_launch(void* const* d_in, const int* in_sizes, int n_in,
                              void* d_out, int out_size) {
    const float* x       = (const float*)d_in[0];   // [2,192,512,512]
    const float* conv_w  = (const float*)d_in[1];   // [192,1,7]
    const float* point_w = (const float*)d_in[2];   // [192,192]
    const float* point_b = (const float*)d_in[3];   // [192]

    fat_kernel<<<FAT_BLKS, 512>>>(x, conv_w, point_w, point_b,
                                  (const float4*)x, (float4*)d_out,
                                  (float*)d_out);
}